// round 1
// baseline (speedup 1.0000x reference)
#include <cuda_runtime.h>

// ---------------- problem constants (compile-time for the hot kernels) ----
#define Hdim   128
#define Odim   32
#define INdim  64
#define RB     32          // batch rows per block
#define NTHR   128         // threads per block (thread = output feature j)
#define MAXB   16384
#define MAXLVL 6           // supports depth <= 5 (expected depth = 4)

// ---------------- static device scratch (no allocations allowed) ----------
__device__ float g_H0  [(size_t)MAXB * Hdim];
__device__ float g_HAI [(size_t)MAXLVL * MAXB * Hdim];
__device__ float g_H2  [(size_t)MAXLVL * MAXB * Hdim];
__device__ float g_PR  [(size_t)(MAXLVL + 1) * MAXB * Odim];

__device__ __forceinline__ float sigmoidf_(float x) {
    return 1.0f / (1.0f + expf(-x));
}

// ---------------- init: hidden = z @ z2h_w + z2h_b ------------------------
__global__ void __launch_bounds__(NTHR)
init_kernel(const float* __restrict__ z, const float* __restrict__ w,
            const float* __restrict__ b, float* __restrict__ hout) {
    __shared__ float zs[RB][INdim];
    const int j    = threadIdx.x;
    const int row0 = blockIdx.x * RB;

    for (int idx = j; idx < RB * INdim; idx += NTHR) {
        int r = idx / INdim, c = idx % INdim;
        zs[r][c] = z[(size_t)(row0 + r) * INdim + c];
    }
    __syncthreads();

    const float bb = b[j];
    for (int r0 = 0; r0 < RB; r0 += 8) {
        float acc[8];
#pragma unroll
        for (int i = 0; i < 8; i++) acc[i] = bb;
        for (int k = 0; k < INdim; k += 4) {
            float4 hv[8];
#pragma unroll
            for (int i = 0; i < 8; i++)
                hv[i] = *reinterpret_cast<const float4*>(&zs[r0 + i][k]);
#pragma unroll
            for (int kk = 0; kk < 4; kk++) {
                float wv = w[(size_t)(k + kk) * Hdim + j];
#pragma unroll
                for (int i = 0; i < 8; i++) {
                    float h = (kk == 0) ? hv[i].x : (kk == 1) ? hv[i].y
                              : (kk == 2) ? hv[i].z : hv[i].w;
                    acc[i] += h * wv;
                }
            }
        }
#pragma unroll
        for (int i = 0; i < 8; i++)
            hout[(size_t)(row0 + r0 + i) * Hdim + j] = acc[i];
    }
}

// ---------------- GRU gates helper (computes h' for 8-row groups) ---------
// hs: [RB][Hdim] hidden in smem, ps: [RB][Odim] x in smem.
// Result h' written via functor-free inline code in each kernel (duplicated
// to keep everything compile-time simple).

// ---------------- fused node kernel ---------------------------------------
// pred = hs@h2o_w + h2o_b  -> pred_out (logits)
// probs = softmax(pred)    -> probs_out
// h_ai  = GRU_a(probs, hs) -> h_out
__global__ void __launch_bounds__(NTHR)
node_kernel(const float* __restrict__ h_a,
            const float* __restrict__ h2o_w, const float* __restrict__ h2o_b,
            const float* __restrict__ wi,    const float* __restrict__ bi,
            const float* __restrict__ wh,    const float* __restrict__ bh,
            float* __restrict__ pred_out, float* __restrict__ probs_out,
            float* __restrict__ h_out) {
    __shared__ float hs[RB][Hdim];
    __shared__ float ps[RB][Odim];
    const int t    = threadIdx.x;
    const int row0 = blockIdx.x * RB;

    for (int idx = t; idx < RB * Hdim; idx += NTHR) {
        int r = idx >> 7, c = idx & 127;
        hs[r][c] = h_a[(size_t)(row0 + r) * Hdim + c];
    }
    __syncthreads();

    // ---- pred + softmax: warp w handles rows w*8 .. w*8+7, lane = o ----
    {
        const int o = t & 31, w = t >> 5;
        float acc[8];
        const float bb = h2o_b[o];
#pragma unroll
        for (int i = 0; i < 8; i++) acc[i] = bb;
        for (int k = 0; k < Hdim; k += 4) {
            float4 hv[8];
#pragma unroll
            for (int i = 0; i < 8; i++)
                hv[i] = *reinterpret_cast<const float4*>(&hs[w * 8 + i][k]);
#pragma unroll
            for (int kk = 0; kk < 4; kk++) {
                float wv = h2o_w[(size_t)(k + kk) * Odim + o];
#pragma unroll
                for (int i = 0; i < 8; i++) {
                    float h = (kk == 0) ? hv[i].x : (kk == 1) ? hv[i].y
                              : (kk == 2) ? hv[i].z : hv[i].w;
                    acc[i] += h * wv;
                }
            }
        }
#pragma unroll
        for (int i = 0; i < 8; i++) {
            int r = w * 8 + i;
            float v = acc[i];
            pred_out[(size_t)(row0 + r) * Odim + o] = v;   // logits
            float m = v;
#pragma unroll
            for (int s = 16; s > 0; s >>= 1)
                m = fmaxf(m, __shfl_xor_sync(0xffffffffu, m, s));
            float e = expf(v - m);
            float ssum = e;
#pragma unroll
            for (int s = 16; s > 0; s >>= 1)
                ssum += __shfl_xor_sync(0xffffffffu, ssum, s);
            float p = e / ssum;
            ps[r][o] = p;
            probs_out[(size_t)(row0 + r) * Odim + o] = p;
        }
    }
    __syncthreads();

    // ---- GRU gates: thread = j, 8-row register blocking ----
    const int j = t;
    const float br_ = bi[0 * Hdim + j] + bh[0 * Hdim + j];
    const float bz_ = bi[1 * Hdim + j] + bh[1 * Hdim + j];
    const float bxn = bi[2 * Hdim + j];
    const float bhn = bh[2 * Hdim + j];

    for (int r0 = 0; r0 < RB; r0 += 8) {
        float ar[8], az[8], ahn[8], axn[8];
#pragma unroll
        for (int i = 0; i < 8; i++) { ar[i] = br_; az[i] = bz_; ahn[i] = bhn; axn[i] = bxn; }

        // h-part: 3 gates over Hdim
        for (int k = 0; k < Hdim; k += 4) {
            float4 hv[8];
#pragma unroll
            for (int i = 0; i < 8; i++)
                hv[i] = *reinterpret_cast<const float4*>(&hs[r0 + i][k]);
#pragma unroll
            for (int kk = 0; kk < 4; kk++) {
                float w0 = wh[0 * Hdim * Hdim + (size_t)(k + kk) * Hdim + j];
                float w1 = wh[1 * Hdim * Hdim + (size_t)(k + kk) * Hdim + j];
                float w2 = wh[2 * Hdim * Hdim + (size_t)(k + kk) * Hdim + j];
#pragma unroll
                for (int i = 0; i < 8; i++) {
                    float h = (kk == 0) ? hv[i].x : (kk == 1) ? hv[i].y
                              : (kk == 2) ? hv[i].z : hv[i].w;
                    ar[i]  += h * w0;
                    az[i]  += h * w1;
                    ahn[i] += h * w2;
                }
            }
        }
        // x-part: 3 gates over Odim
        for (int k = 0; k < Odim; k += 4) {
            float4 pv[8];
#pragma unroll
            for (int i = 0; i < 8; i++)
                pv[i] = *reinterpret_cast<const float4*>(&ps[r0 + i][k]);
#pragma unroll
            for (int kk = 0; kk < 4; kk++) {
                float w0 = wi[0 * Odim * Hdim + (size_t)(k + kk) * Hdim + j];
                float w1 = wi[1 * Odim * Hdim + (size_t)(k + kk) * Hdim + j];
                float w2 = wi[2 * Odim * Hdim + (size_t)(k + kk) * Hdim + j];
#pragma unroll
                for (int i = 0; i < 8; i++) {
                    float x = (kk == 0) ? pv[i].x : (kk == 1) ? pv[i].y
                              : (kk == 2) ? pv[i].z : pv[i].w;
                    ar[i]  += x * w0;
                    az[i]  += x * w1;
                    axn[i] += x * w2;
                }
            }
        }
#pragma unroll
        for (int i = 0; i < 8; i++) {
            float rg = sigmoidf_(ar[i]);
            float zg = sigmoidf_(az[i]);
            float n  = tanhf(axn[i] + rg * ahn[i]);
            float hv = hs[r0 + i][j];
            h_out[(size_t)(row0 + r0 + i) * Hdim + j] = (1.0f - zg) * n + zg * hv;
        }
    }
}

// ---------------- fused combine kernel ------------------------------------
// h_f = GRU_f(probs_fc, h_ai); h2 = tanh(h_f@u_f_w + u_f_b + h_a@u_a_w + u_a_b)
__global__ void __launch_bounds__(NTHR)
combine_kernel(const float* __restrict__ probs_fc,
               const float* __restrict__ h_ai, const float* __restrict__ h_a,
               const float* __restrict__ wi,  const float* __restrict__ bi,
               const float* __restrict__ wh,  const float* __restrict__ bh,
               const float* __restrict__ ufw, const float* __restrict__ ufb,
               const float* __restrict__ uaw, const float* __restrict__ uab,
               float* __restrict__ h2_out) {
    __shared__ float hs[RB][Hdim];   // h_ai, later reloaded with h_a
    __shared__ float ps[RB][Odim];   // probs of first child
    __shared__ float hf[RB][Hdim];   // GRU_f output
    const int t    = threadIdx.x;
    const int row0 = blockIdx.x * RB;

    for (int idx = t; idx < RB * Hdim; idx += NTHR) {
        int r = idx >> 7, c = idx & 127;
        hs[r][c] = h_ai[(size_t)(row0 + r) * Hdim + c];
    }
    for (int idx = t; idx < RB * Odim; idx += NTHR) {
        int r = idx >> 5, c = idx & 31;
        ps[r][c] = probs_fc[(size_t)(row0 + r) * Odim + c];
    }
    __syncthreads();

    const int j = t;
    {
        const float br_ = bi[0 * Hdim + j] + bh[0 * Hdim + j];
        const float bz_ = bi[1 * Hdim + j] + bh[1 * Hdim + j];
        const float bxn = bi[2 * Hdim + j];
        const float bhn = bh[2 * Hdim + j];

        for (int r0 = 0; r0 < RB; r0 += 8) {
            float ar[8], az[8], ahn[8], axn[8];
#pragma unroll
            for (int i = 0; i < 8; i++) { ar[i] = br_; az[i] = bz_; ahn[i] = bhn; axn[i] = bxn; }

            for (int k = 0; k < Hdim; k += 4) {
                float4 hv[8];
#pragma unroll
                for (int i = 0; i < 8; i++)
                    hv[i] = *reinterpret_cast<const float4*>(&hs[r0 + i][k]);
#pragma unroll
                for (int kk = 0; kk < 4; kk++) {
                    float w0 = wh[0 * Hdim * Hdim + (size_t)(k + kk) * Hdim + j];
                    float w1 = wh[1 * Hdim * Hdim + (size_t)(k + kk) * Hdim + j];
                    float w2 = wh[2 * Hdim * Hdim + (size_t)(k + kk) * Hdim + j];
#pragma unroll
                    for (int i = 0; i < 8; i++) {
                        float h = (kk == 0) ? hv[i].x : (kk == 1) ? hv[i].y
                                  : (kk == 2) ? hv[i].z : hv[i].w;
                        ar[i]  += h * w0;
                        az[i]  += h * w1;
                        ahn[i] += h * w2;
                    }
                }
            }
            for (int k = 0; k < Odim; k += 4) {
                float4 pv[8];
#pragma unroll
                for (int i = 0; i < 8; i++)
                    pv[i] = *reinterpret_cast<const float4*>(&ps[r0 + i][k]);
#pragma unroll
                for (int kk = 0; kk < 4; kk++) {
                    float w0 = wi[0 * Odim * Hdim + (size_t)(k + kk) * Hdim + j];
                    float w1 = wi[1 * Odim * Hdim + (size_t)(k + kk) * Hdim + j];
                    float w2 = wi[2 * Odim * Hdim + (size_t)(k + kk) * Hdim + j];
#pragma unroll
                    for (int i = 0; i < 8; i++) {
                        float x = (kk == 0) ? pv[i].x : (kk == 1) ? pv[i].y
                                  : (kk == 2) ? pv[i].z : pv[i].w;
                        ar[i]  += x * w0;
                        az[i]  += x * w1;
                        axn[i] += x * w2;
                    }
                }
            }
#pragma unroll
            for (int i = 0; i < 8; i++) {
                float rg = sigmoidf_(ar[i]);
                float zg = sigmoidf_(az[i]);
                float n  = tanhf(axn[i] + rg * ahn[i]);
                float hv = hs[r0 + i][j];
                hf[r0 + i][j] = (1.0f - zg) * n + zg * hv;
            }
        }
    }
    __syncthreads();
    // reload hs with h_a for the merge stage
    for (int idx = t; idx < RB * Hdim; idx += NTHR) {
        int r = idx >> 7, c = idx & 127;
        hs[r][c] = h_a[(size_t)(row0 + r) * Hdim + c];
    }
    __syncthreads();

    // h2 = tanh(hf@ufw + hs@uaw + ufb + uab)
    const float bb = ufb[j] + uab[j];
    for (int r0 = 0; r0 < RB; r0 += 8) {
        float acc[8];
#pragma unroll
        for (int i = 0; i < 8; i++) acc[i] = bb;

        for (int k = 0; k < Hdim; k += 4) {           // hf part
            float4 hv[8];
#pragma unroll
            for (int i = 0; i < 8; i++)
                hv[i] = *reinterpret_cast<const float4*>(&hf[r0 + i][k]);
#pragma unroll
            for (int kk = 0; kk < 4; kk++) {
                float wv = ufw[(size_t)(k + kk) * Hdim + j];
#pragma unroll
                for (int i = 0; i < 8; i++) {
                    float h = (kk == 0) ? hv[i].x : (kk == 1) ? hv[i].y
                              : (kk == 2) ? hv[i].z : hv[i].w;
                    acc[i] += h * wv;
                }
            }
        }
        for (int k = 0; k < Hdim; k += 4) {           // h_a part
            float4 hv[8];
#pragma unroll
            for (int i = 0; i < 8; i++)
                hv[i] = *reinterpret_cast<const float4*>(&hs[r0 + i][k]);
#pragma unroll
            for (int kk = 0; kk < 4; kk++) {
                float wv = uaw[(size_t)(k + kk) * Hdim + j];
#pragma unroll
                for (int i = 0; i < 8; i++) {
                    float h = (kk == 0) ? hv[i].x : (kk == 1) ? hv[i].y
                              : (kk == 2) ? hv[i].z : hv[i].w;
                    acc[i] += h * wv;
                }
            }
        }
#pragma unroll
        for (int i = 0; i < 8; i++)
            h2_out[(size_t)(row0 + r0 + i) * Hdim + j] = tanhf(acc[i]);
    }
}

// ---------------- host-side tree orchestration ----------------------------
struct EmitCtx {
    const float *h2o_w, *h2o_b;
    const float *awi, *abi, *awh, *abh;
    const float *fwi, *fbi, *fwh, *fbh;
    const float *uaw, *uab, *ufw, *ufb;
    float* out;
    float *HAI, *H2, *PR;
    int B, grid, idx;
};

static void emit_node(EmitCtx& P, int lvl, int d, const float* h_in) {
    float* probs = P.PR  + (size_t)lvl * P.B * Odim;
    float* h_ai  = P.HAI + (size_t)lvl * P.B * Hdim;
    node_kernel<<<P.grid, NTHR>>>(h_in, P.h2o_w, P.h2o_b,
                                  P.awi, P.abi, P.awh, P.abh,
                                  P.out + (size_t)P.idx * P.B * Odim,
                                  probs, h_ai);
    P.idx++;
    if (d > 0) {
        emit_node(P, lvl + 1, d - 1, h_ai);              // first child
        float* h2 = P.H2 + (size_t)lvl * P.B * Hdim;
        combine_kernel<<<P.grid, NTHR>>>(P.PR + (size_t)(lvl + 1) * P.B * Odim,
                                         h_ai, h_in,
                                         P.fwi, P.fbi, P.fwh, P.fbh,
                                         P.ufw, P.ufb, P.uaw, P.uab, h2);
        emit_node(P, lvl + 1, d - 1, h2);                // second child
    }
}

extern "C" void kernel_launch(void* const* d_in, const int* in_sizes, int n_in,
                              void* d_out, int out_size) {
    const float* z      = (const float*)d_in[0];
    const float* z2h_w  = (const float*)d_in[1];
    const float* z2h_b  = (const float*)d_in[2];

    EmitCtx P;
    P.h2o_w = (const float*)d_in[3];   P.h2o_b = (const float*)d_in[4];
    P.awi   = (const float*)d_in[5];   P.abi   = (const float*)d_in[6];
    P.awh   = (const float*)d_in[7];   P.abh   = (const float*)d_in[8];
    P.fwi   = (const float*)d_in[9];   P.fbi   = (const float*)d_in[10];
    P.fwh   = (const float*)d_in[11];  P.fbh   = (const float*)d_in[12];
    P.uaw   = (const float*)d_in[13];  P.uab   = (const float*)d_in[14];
    P.ufw   = (const float*)d_in[15];  P.ufb   = (const float*)d_in[16];
    P.out   = (float*)d_out;

    const int H  = in_sizes[2];               // 128
    const int O  = in_sizes[4];               // 32
    const int IN = in_sizes[1] / H;           // 64
    const int B  = in_sizes[0] / IN;          // 16384
    const int nn = out_size / (B * O);        // number of tree nodes (31)
    int depth = 0;
    while (((2 << depth) - 1) < nn) depth++;  // nn = 2^(depth+1)-1

    float *H0p, *HAIp, *H2p, *PRp;
    cudaGetSymbolAddress((void**)&H0p,  g_H0);
    cudaGetSymbolAddress((void**)&HAIp, g_HAI);
    cudaGetSymbolAddress((void**)&H2p,  g_H2);
    cudaGetSymbolAddress((void**)&PRp,  g_PR);

    P.HAI = HAIp; P.H2 = H2p; P.PR = PRp;
    P.B = B; P.grid = B / RB; P.idx = 0;

    init_kernel<<<P.grid, NTHR>>>(z, z2h_w, z2h_b, H0p);
    emit_node(P, 0, depth, H0p);
}

// round 2
// speedup vs baseline: 1.1916x; 1.1916x over previous
#include <cuda_runtime.h>

// ---------------- problem constants ---------------------------------------
#define Hdim   128
#define Odim   32
#define INdim  64
#define RB     16          // batch rows per block
#define NTHR   128         // threads per block (thread = output feature j)
#define MAXB   16384
#define MAXLVL 6

// ---------------- static device scratch (no allocations allowed) ----------
__device__ float g_H0  [(size_t)MAXB * Hdim];
__device__ float g_HAI [(size_t)MAXLVL * MAXB * Hdim];
__device__ float g_H2  [(size_t)MAXLVL * MAXB * Hdim];
__device__ float g_PR  [(size_t)(MAXLVL + 1) * MAXB * Odim];

// packed weights: [k4][j][4] layout per matrix (gates folded into k)
//   WH_A: 3*128*128 = 49152   @ 0
//   WI_A: 3* 32*128 = 12288   @ 49152
//   WH_F: 49152               @ 61440
//   WI_F: 12288               @ 110592
//   UF  : 128*128   = 16384   @ 122880
//   UA  : 16384               @ 139264
#define OFF_WH_A 0
#define OFF_WI_A 49152
#define OFF_WH_F 61440
#define OFF_WI_F 110592
#define OFF_UF   122880
#define OFF_UA   139264
__device__ float g_WP[155648];

typedef unsigned long long u64;
union F4U { float4 f; ulonglong2 u; };

__device__ __forceinline__ void ffma2(u64& d, u64 a, u64 b) {
    asm volatile("fma.rn.f32x2 %0, %1, %2, %0;" : "+l"(d) : "l"(a), "l"(b));
}
__device__ __forceinline__ u64 pack2(float lo, float hi) {
    u64 r; asm("mov.b64 %0, {%1, %2};" : "=l"(r) : "f"(lo), "f"(hi)); return r;
}
__device__ __forceinline__ float f2sum(u64 v) {
    float lo, hi; asm("mov.b64 {%0, %1}, %2;" : "=f"(lo), "=f"(hi) : "l"(v));
    return lo + hi;
}
__device__ __forceinline__ float sigmoidf_(float x) {
    return 1.0f / (1.0f + expf(-x));
}

// ---------------- weight repack prologue ----------------------------------
// src is [Ktot][128] row-major; dst group g: k4 = g>>7, j = g&127,
// dst[g*4 + t] = src[(4*k4+t)*128 + j]
__device__ __forceinline__ void pack_one(const float* __restrict__ src,
                                         float* __restrict__ dst, int g) {
    int k4 = g >> 7, j = g & 127;
    float4 v;
    v.x = src[(size_t)(4 * k4 + 0) * 128 + j];
    v.y = src[(size_t)(4 * k4 + 1) * 128 + j];
    v.z = src[(size_t)(4 * k4 + 2) * 128 + j];
    v.w = src[(size_t)(4 * k4 + 3) * 128 + j];
    *reinterpret_cast<float4*>(dst + (size_t)g * 4) = v;
}

__global__ void pack_kernel(const float* __restrict__ awh, const float* __restrict__ awi,
                            const float* __restrict__ fwh, const float* __restrict__ fwi,
                            const float* __restrict__ ufw, const float* __restrict__ uaw,
                            float* __restrict__ WP) {
    int g = blockIdx.x * blockDim.x + threadIdx.x;
    if      (g < 12288) pack_one(awh, WP + OFF_WH_A, g);
    else if (g < 15360) pack_one(awi, WP + OFF_WI_A, g - 12288);
    else if (g < 27648) pack_one(fwh, WP + OFF_WH_F, g - 15360);
    else if (g < 30720) pack_one(fwi, WP + OFF_WI_F, g - 27648);
    else if (g < 34816) pack_one(ufw, WP + OFF_UF,   g - 30720);
    else if (g < 38912) pack_one(uaw, WP + OFF_UA,   g - 34816);
}

// ---------------- init: hidden = z @ z2h_w + z2h_b ------------------------
__global__ void __launch_bounds__(NTHR)
init_kernel(const float* __restrict__ z, const float* __restrict__ w,
            const float* __restrict__ b, float* __restrict__ hout) {
    __shared__ float zs[RB][INdim];
    const int j    = threadIdx.x;
    const int row0 = blockIdx.x * RB;

    {
        const float4* src = reinterpret_cast<const float4*>(z + (size_t)row0 * INdim);
        float4* dst = reinterpret_cast<float4*>(&zs[0][0]);
        for (int i = j; i < RB * INdim / 4; i += NTHR) dst[i] = src[i];
    }
    __syncthreads();

    const float bb = b[j];
    for (int r0 = 0; r0 < RB; r0 += 4) {
        float acc[4];
#pragma unroll
        for (int i = 0; i < 4; i++) acc[i] = bb;
        for (int k = 0; k < INdim; k += 4) {
            float4 hv[4];
#pragma unroll
            for (int i = 0; i < 4; i++)
                hv[i] = *reinterpret_cast<const float4*>(&zs[r0 + i][k]);
#pragma unroll
            for (int kk = 0; kk < 4; kk++) {
                float wv = w[(size_t)(k + kk) * Hdim + j];
#pragma unroll
                for (int i = 0; i < 4; i++) {
                    float h = (kk == 0) ? hv[i].x : (kk == 1) ? hv[i].y
                              : (kk == 2) ? hv[i].z : hv[i].w;
                    acc[i] += h * wv;
                }
            }
        }
#pragma unroll
        for (int i = 0; i < 4; i++)
            hout[(size_t)(row0 + r0 + i) * Hdim + j] = acc[i];
    }
}

// ---------------- GRU gate core (packed FFMA2) ----------------------------
// hs: [RB][Hdim] smem, ps: [RB][Odim] smem. Computes h' for rows r0..r0+3
// using packed weights whP (3 gates, K=Hdim) and wiP (3 gates, K=Odim).
// Writes results via caller-provided lambda-free epilogue: returns in out[4].
__device__ __forceinline__ void gru_rows4(
    const float (*hs)[Hdim], const float (*ps)[Odim], int r0, int j,
    const float* __restrict__ whP, const float* __restrict__ wiP,
    const float* __restrict__ bi, const float* __restrict__ bh,
    float out[4]) {
    const float br_ = bi[0 * Hdim + j] + bh[0 * Hdim + j];
    const float bz_ = bi[1 * Hdim + j] + bh[1 * Hdim + j];
    const float bxn = bi[2 * Hdim + j];
    const float bhn = bh[2 * Hdim + j];

    u64 ar[4], az[4], anh[4], anx[4];
#pragma unroll
    for (int i = 0; i < 4; i++) {
        ar[i]  = pack2(br_, 0.0f);
        az[i]  = pack2(bz_, 0.0f);
        anh[i] = pack2(bhn, 0.0f);
        anx[i] = pack2(bxn, 0.0f);
    }

    const float4* WH = reinterpret_cast<const float4*>(whP);
#pragma unroll 2
    for (int k4 = 0; k4 < Hdim / 4; k4++) {
        F4U w0, w1, w2;
        w0.f = WH[(size_t)(0 * 32 + k4) * 128 + j];
        w1.f = WH[(size_t)(1 * 32 + k4) * 128 + j];
        w2.f = WH[(size_t)(2 * 32 + k4) * 128 + j];
        ulonglong2 h[4];
#pragma unroll
        for (int i = 0; i < 4; i++)
            h[i] = *reinterpret_cast<const ulonglong2*>(&hs[r0 + i][k4 * 4]);
#pragma unroll
        for (int i = 0; i < 4; i++) {
            ffma2(ar[i],  h[i].x, w0.u.x); ffma2(az[i],  h[i].x, w1.u.x);
            ffma2(anh[i], h[i].x, w2.u.x);
            ffma2(ar[i],  h[i].y, w0.u.y); ffma2(az[i],  h[i].y, w1.u.y);
            ffma2(anh[i], h[i].y, w2.u.y);
        }
    }

    const float4* WI = reinterpret_cast<const float4*>(wiP);
#pragma unroll 2
    for (int k4 = 0; k4 < Odim / 4; k4++) {
        F4U w0, w1, w2;
        w0.f = WI[(size_t)(0 * 8 + k4) * 128 + j];
        w1.f = WI[(size_t)(1 * 8 + k4) * 128 + j];
        w2.f = WI[(size_t)(2 * 8 + k4) * 128 + j];
        ulonglong2 p[4];
#pragma unroll
        for (int i = 0; i < 4; i++)
            p[i] = *reinterpret_cast<const ulonglong2*>(&ps[r0 + i][k4 * 4]);
#pragma unroll
        for (int i = 0; i < 4; i++) {
            ffma2(ar[i],  p[i].x, w0.u.x); ffma2(az[i],  p[i].x, w1.u.x);
            ffma2(anx[i], p[i].x, w2.u.x);
            ffma2(ar[i],  p[i].y, w0.u.y); ffma2(az[i],  p[i].y, w1.u.y);
            ffma2(anx[i], p[i].y, w2.u.y);
        }
    }

#pragma unroll
    for (int i = 0; i < 4; i++) {
        float rg = sigmoidf_(f2sum(ar[i]));
        float zg = sigmoidf_(f2sum(az[i]));
        float n  = tanhf(f2sum(anx[i]) + rg * f2sum(anh[i]));
        float hv = hs[r0 + i][j];
        out[i] = (1.0f - zg) * n + zg * hv;
    }
}

// ---------------- fused node kernel ---------------------------------------
__global__ void __launch_bounds__(NTHR)
node_kernel(const float* __restrict__ h_a,
            const float* __restrict__ h2o_w, const float* __restrict__ h2o_b,
            const float* __restrict__ wiP,   const float* __restrict__ bi,
            const float* __restrict__ whP,   const float* __restrict__ bh,
            float* __restrict__ pred_out, float* __restrict__ probs_out,
            float* __restrict__ h_out) {
    __shared__ float hs[RB][Hdim];
    __shared__ float ps[RB][Odim];
    const int t    = threadIdx.x;
    const int row0 = blockIdx.x * RB;

    {
        const float4* src = reinterpret_cast<const float4*>(h_a + (size_t)row0 * Hdim);
        float4* dst = reinterpret_cast<float4*>(&hs[0][0]);
        for (int i = t; i < RB * Hdim / 4; i += NTHR) dst[i] = src[i];
    }
    __syncthreads();

    // ---- pred + softmax: warp w handles rows w*4..w*4+3, lane = o ----
    {
        const int o = t & 31, w = t >> 5;
        float acc[4];
        const float bb = h2o_b[o];
#pragma unroll
        for (int i = 0; i < 4; i++) acc[i] = bb;
        for (int k = 0; k < Hdim; k += 4) {
            float4 hv[4];
#pragma unroll
            for (int i = 0; i < 4; i++)
                hv[i] = *reinterpret_cast<const float4*>(&hs[w * 4 + i][k]);
#pragma unroll
            for (int kk = 0; kk < 4; kk++) {
                float wv = h2o_w[(size_t)(k + kk) * Odim + o];
#pragma unroll
                for (int i = 0; i < 4; i++) {
                    float h = (kk == 0) ? hv[i].x : (kk == 1) ? hv[i].y
                              : (kk == 2) ? hv[i].z : hv[i].w;
                    acc[i] += h * wv;
                }
            }
        }
#pragma unroll
        for (int i = 0; i < 4; i++) {
            int r = w * 4 + i;
            float v = acc[i];
            pred_out[(size_t)(row0 + r) * Odim + o] = v;
            float m = v;
#pragma unroll
            for (int s = 16; s > 0; s >>= 1)
                m = fmaxf(m, __shfl_xor_sync(0xffffffffu, m, s));
            float e = expf(v - m);
            float ssum = e;
#pragma unroll
            for (int s = 16; s > 0; s >>= 1)
                ssum += __shfl_xor_sync(0xffffffffu, ssum, s);
            float p = e / ssum;
            ps[r][o] = p;
            probs_out[(size_t)(row0 + r) * Odim + o] = p;
        }
    }
    __syncthreads();

    const int j = t;
    for (int r0 = 0; r0 < RB; r0 += 4) {
        float out[4];
        gru_rows4(hs, ps, r0, j, whP, wiP, bi, bh, out);
#pragma unroll
        for (int i = 0; i < 4; i++)
            h_out[(size_t)(row0 + r0 + i) * Hdim + j] = out[i];
    }
}

// ---------------- fused combine kernel ------------------------------------
__global__ void __launch_bounds__(NTHR)
combine_kernel(const float* __restrict__ probs_fc,
               const float* __restrict__ h_ai, const float* __restrict__ h_a,
               const float* __restrict__ wiP,  const float* __restrict__ bi,
               const float* __restrict__ whP,  const float* __restrict__ bh,
               const float* __restrict__ ufP,  const float* __restrict__ ufb,
               const float* __restrict__ uaP,  const float* __restrict__ uab,
               float* __restrict__ h2_out) {
    __shared__ float hs[RB][Hdim];   // h_ai, later reloaded with h_a
    __shared__ float ps[RB][Odim];
    __shared__ float hf[RB][Hdim];
    const int t    = threadIdx.x;
    const int row0 = blockIdx.x * RB;

    {
        const float4* src = reinterpret_cast<const float4*>(h_ai + (size_t)row0 * Hdim);
        float4* dst = reinterpret_cast<float4*>(&hs[0][0]);
        for (int i = t; i < RB * Hdim / 4; i += NTHR) dst[i] = src[i];
        const float4* psrc = reinterpret_cast<const float4*>(probs_fc + (size_t)row0 * Odim);
        float4* pdst = reinterpret_cast<float4*>(&ps[0][0]);
        for (int i = t; i < RB * Odim / 4; i += NTHR) pdst[i] = psrc[i];
    }
    __syncthreads();

    const int j = t;
    for (int r0 = 0; r0 < RB; r0 += 4) {
        float out[4];
        gru_rows4(hs, ps, r0, j, whP, wiP, bi, bh, out);
#pragma unroll
        for (int i = 0; i < 4; i++)
            hf[r0 + i][j] = out[i];
    }
    __syncthreads();
    // reload hs with h_a
    {
        const float4* src = reinterpret_cast<const float4*>(h_a + (size_t)row0 * Hdim);
        float4* dst = reinterpret_cast<float4*>(&hs[0][0]);
        for (int i = t; i < RB * Hdim / 4; i += NTHR) dst[i] = src[i];
    }
    __syncthreads();

    // h2 = tanh(hf@ufw + hs@uaw + ufb + uab)  — packed FFMA2
    const float bb = ufb[j] + uab[j];
    const float4* UF = reinterpret_cast<const float4*>(ufP);
    const float4* UA = reinterpret_cast<const float4*>(uaP);
    for (int r0 = 0; r0 < RB; r0 += 4) {
        u64 acc[4];
#pragma unroll
        for (int i = 0; i < 4; i++) acc[i] = pack2(bb, 0.0f);
#pragma unroll 2
        for (int k4 = 0; k4 < Hdim / 4; k4++) {
            F4U wf, wa;
            wf.f = UF[(size_t)k4 * 128 + j];
            wa.f = UA[(size_t)k4 * 128 + j];
            ulonglong2 hv[4], av[4];
#pragma unroll
            for (int i = 0; i < 4; i++) {
                hv[i] = *reinterpret_cast<const ulonglong2*>(&hf[r0 + i][k4 * 4]);
                av[i] = *reinterpret_cast<const ulonglong2*>(&hs[r0 + i][k4 * 4]);
            }
#pragma unroll
            for (int i = 0; i < 4; i++) {
                ffma2(acc[i], hv[i].x, wf.u.x); ffma2(acc[i], hv[i].y, wf.u.y);
                ffma2(acc[i], av[i].x, wa.u.x); ffma2(acc[i], av[i].y, wa.u.y);
            }
        }
#pragma unroll
        for (int i = 0; i < 4; i++)
            h2_out[(size_t)(row0 + r0 + i) * Hdim + j] = tanhf(f2sum(acc[i]));
    }
}

// ---------------- host-side tree orchestration ----------------------------
struct EmitCtx {
    const float *h2o_w, *h2o_b;
    const float *abi, *abh, *fbi, *fbh;
    const float *uab, *ufb;
    const float *awiP, *awhP, *fwiP, *fwhP, *ufP, *uaP;
    float* out;
    float *HAI, *H2, *PR;
    int B, grid, idx;
};

static void emit_node(EmitCtx& P, int lvl, int d, const float* h_in) {
    float* probs = P.PR  + (size_t)lvl * P.B * Odim;
    float* h_ai  = P.HAI + (size_t)lvl * P.B * Hdim;
    node_kernel<<<P.grid, NTHR>>>(h_in, P.h2o_w, P.h2o_b,
                                  P.awiP, P.abi, P.awhP, P.abh,
                                  P.out + (size_t)P.idx * P.B * Odim,
                                  probs, h_ai);
    P.idx++;
    if (d > 0) {
        emit_node(P, lvl + 1, d - 1, h_ai);
        float* h2 = P.H2 + (size_t)lvl * P.B * Hdim;
        combine_kernel<<<P.grid, NTHR>>>(P.PR + (size_t)(lvl + 1) * P.B * Odim,
                                         h_ai, h_in,
                                         P.fwiP, P.fbi, P.fwhP, P.fbh,
                                         P.ufP, P.ufb, P.uaP, P.uab, h2);
        emit_node(P, lvl + 1, d - 1, h2);
    }
}

extern "C" void kernel_launch(void* const* d_in, const int* in_sizes, int n_in,
                              void* d_out, int out_size) {
    const float* z      = (const float*)d_in[0];
    const float* z2h_w  = (const float*)d_in[1];
    const float* z2h_b  = (const float*)d_in[2];

    const float* h2o_w  = (const float*)d_in[3];
    const float* h2o_b  = (const float*)d_in[4];
    const float* awi    = (const float*)d_in[5];
    const float* abi    = (const float*)d_in[6];
    const float* awh    = (const float*)d_in[7];
    const float* abh    = (const float*)d_in[8];
    const float* fwi    = (const float*)d_in[9];
    const float* fbi    = (const float*)d_in[10];
    const float* fwh    = (const float*)d_in[11];
    const float* fbh    = (const float*)d_in[12];
    const float* uaw    = (const float*)d_in[13];
    const float* uab    = (const float*)d_in[14];
    const float* ufw    = (const float*)d_in[15];
    const float* ufb    = (const float*)d_in[16];

    const int H  = in_sizes[2];               // 128
    const int O  = in_sizes[4];               // 32
    const int IN = in_sizes[1] / H;           // 64
    const int B  = in_sizes[0] / IN;          // 16384
    const int nn = out_size / (B * O);        // tree nodes (31)
    int depth = 0;
    while (((2 << depth) - 1) < nn) depth++;

    float *H0p, *HAIp, *H2p, *PRp, *WPp;
    cudaGetSymbolAddress((void**)&H0p,  g_H0);
    cudaGetSymbolAddress((void**)&HAIp, g_HAI);
    cudaGetSymbolAddress((void**)&H2p,  g_H2);
    cudaGetSymbolAddress((void**)&PRp,  g_PR);
    cudaGetSymbolAddress((void**)&WPp,  g_WP);

    // weight repack prologue (38912 float4 groups)
    pack_kernel<<<(38912 + 255) / 256, 256>>>(awh, awi, fwh, fwi, ufw, uaw, WPp);

    EmitCtx P;
    P.h2o_w = h2o_w; P.h2o_b = h2o_b;
    P.abi = abi; P.abh = abh; P.fbi = fbi; P.fbh = fbh;
    P.uab = uab; P.ufb = ufb;
    P.awiP = WPp + OFF_WI_A; P.awhP = WPp + OFF_WH_A;
    P.fwiP = WPp + OFF_WI_F; P.fwhP = WPp + OFF_WH_F;
    P.ufP  = WPp + OFF_UF;   P.uaP  = WPp + OFF_UA;
    P.out  = (float*)d_out;
    P.HAI = HAIp; P.H2 = H2p; P.PR = PRp;
    P.B = B; P.grid = B / RB; P.idx = 0;

    init_kernel<<<P.grid, NTHR>>>(z, z2h_w, z2h_b, H0p);
    emit_node(P, 0, depth, H0p);
}

// round 3
// speedup vs baseline: 1.1941x; 1.0021x over previous
#include <cuda_runtime.h>

// ---------------- problem constants ---------------------------------------
#define Hdim   128
#define Odim   32
#define INdim  64
#define RB     16          // batch rows per block
#define NTHR   128         // threads per block (thread = output feature j)
#define MAXB   16384
#define MAXLVL 6

// ---------------- static device scratch (no allocations allowed) ----------
__device__ float g_H0  [(size_t)MAXB * Hdim];
__device__ float g_HAI [(size_t)MAXLVL * MAXB * Hdim];
__device__ float g_H2  [(size_t)MAXLVL * MAXB * Hdim];
__device__ float g_PR  [(size_t)(MAXLVL + 1) * MAXB * Odim];

// packed weights: [k4][j][4] layout per matrix (gates folded into k)
//   WH_A: 3*128*128 = 49152   @ 0
//   WI_A: 3* 32*128 = 12288   @ 49152
//   WH_F: 49152               @ 61440
//   WI_F: 12288               @ 110592
//   UF  : 128*128   = 16384   @ 122880
//   UA  : 16384               @ 139264
#define OFF_WH_A 0
#define OFF_WI_A 49152
#define OFF_WH_F 61440
#define OFF_WI_F 110592
#define OFF_UF   122880
#define OFF_UA   139264
__device__ float g_WP[155648];

typedef unsigned long long u64;
union F4U { float4 f; ulonglong2 u; };

__device__ __forceinline__ void ffma2(u64& d, u64 a, u64 b) {
    asm volatile("fma.rn.f32x2 %0, %1, %2, %0;" : "+l"(d) : "l"(a), "l"(b));
}
__device__ __forceinline__ u64 pack2(float lo, float hi) {
    u64 r; asm("mov.b64 %0, {%1, %2};" : "=l"(r) : "f"(lo), "f"(hi)); return r;
}
__device__ __forceinline__ float f2sum(u64 v) {
    float lo, hi; asm("mov.b64 {%0, %1}, %2;" : "=f"(lo), "=f"(hi) : "l"(v));
    return lo + hi;
}
__device__ __forceinline__ float sigmoidf_(float x) {
    return 1.0f / (1.0f + expf(-x));
}

// ---------------- weight repack prologue ----------------------------------
// src is [Ktot][128] row-major; dst group g: k4 = g>>7, j = g&127,
// dst[g*4 + t] = src[(4*k4+t)*128 + j]
__device__ __forceinline__ void pack_one(const float* __restrict__ src,
                                         float* __restrict__ dst, int g) {
    int k4 = g >> 7, j = g & 127;
    float4 v;
    v.x = src[(size_t)(4 * k4 + 0) * 128 + j];
    v.y = src[(size_t)(4 * k4 + 1) * 128 + j];
    v.z = src[(size_t)(4 * k4 + 2) * 128 + j];
    v.w = src[(size_t)(4 * k4 + 3) * 128 + j];
    *reinterpret_cast<float4*>(dst + (size_t)g * 4) = v;
}

__global__ void pack_kernel(const float* __restrict__ awh, const float* __restrict__ awi,
                            const float* __restrict__ fwh, const float* __restrict__ fwi,
                            const float* __restrict__ ufw, const float* __restrict__ uaw,
                            float* __restrict__ WP) {
    int g = blockIdx.x * blockDim.x + threadIdx.x;
    if      (g < 12288) pack_one(awh, WP + OFF_WH_A, g);
    else if (g < 15360) pack_one(awi, WP + OFF_WI_A, g - 12288);
    else if (g < 27648) pack_one(fwh, WP + OFF_WH_F, g - 15360);
    else if (g < 30720) pack_one(fwi, WP + OFF_WI_F, g - 27648);
    else if (g < 34816) pack_one(ufw, WP + OFF_UF,   g - 30720);
    else if (g < 38912) pack_one(uaw, WP + OFF_UA,   g - 34816);
}

// ---------------- init: hidden = z @ z2h_w + z2h_b ------------------------
__global__ void __launch_bounds__(NTHR)
init_kernel(const float* __restrict__ z, const float* __restrict__ w,
            const float* __restrict__ b, float* __restrict__ hout) {
    __shared__ float zs[RB][INdim];
    const int j    = threadIdx.x;
    const int row0 = blockIdx.x * RB;

    {
        const float4* src = reinterpret_cast<const float4*>(z + (size_t)row0 * INdim);
        float4* dst = reinterpret_cast<float4*>(&zs[0][0]);
        for (int i = j; i < RB * INdim / 4; i += NTHR) dst[i] = src[i];
    }
    __syncthreads();

    const float bb = b[j];
    for (int r0 = 0; r0 < RB; r0 += 4) {
        float acc[4];
#pragma unroll
        for (int i = 0; i < 4; i++) acc[i] = bb;
        for (int k = 0; k < INdim; k += 4) {
            float4 hv[4];
#pragma unroll
            for (int i = 0; i < 4; i++)
                hv[i] = *reinterpret_cast<const float4*>(&zs[r0 + i][k]);
#pragma unroll
            for (int kk = 0; kk < 4; kk++) {
                float wv = w[(size_t)(k + kk) * Hdim + j];
#pragma unroll
                for (int i = 0; i < 4; i++) {
                    float h = (kk == 0) ? hv[i].x : (kk == 1) ? hv[i].y
                              : (kk == 2) ? hv[i].z : hv[i].w;
                    acc[i] += h * wv;
                }
            }
        }
#pragma unroll
        for (int i = 0; i < 4; i++)
            hout[(size_t)(row0 + r0 + i) * Hdim + j] = acc[i];
    }
}

// ---------------- GRU gate core (packed FFMA2) ----------------------------
// hs: [RB][Hdim] smem, ps: [RB][Odim] smem. Computes h' for rows r0..r0+3
// using packed weights whP (3 gates, K=Hdim) and wiP (3 gates, K=Odim).
// Writes results via caller-provided lambda-free epilogue: returns in out[4].
__device__ __forceinline__ void gru_rows4(
    const float (*hs)[Hdim], const float (*ps)[Odim], int r0, int j,
    const float* __restrict__ whP, const float* __restrict__ wiP,
    const float* __restrict__ bi, const float* __restrict__ bh,
    float out[4]) {
    const float br_ = bi[0 * Hdim + j] + bh[0 * Hdim + j];
    const float bz_ = bi[1 * Hdim + j] + bh[1 * Hdim + j];
    const float bxn = bi[2 * Hdim + j];
    const float bhn = bh[2 * Hdim + j];

    u64 ar[4], az[4], anh[4], anx[4];
#pragma unroll
    for (int i = 0; i < 4; i++) {
        ar[i]  = pack2(br_, 0.0f);
        az[i]  = pack2(bz_, 0.0f);
        anh[i] = pack2(bhn, 0.0f);
        anx[i] = pack2(bxn, 0.0f);
    }

    const float4* WH = reinterpret_cast<const float4*>(whP);
#pragma unroll 2
    for (int k4 = 0; k4 < Hdim / 4; k4++) {
        F4U w0, w1, w2;
        w0.f = WH[(size_t)(0 * 32 + k4) * 128 + j];
        w1.f = WH[(size_t)(1 * 32 + k4) * 128 + j];
        w2.f = WH[(size_t)(2 * 32 + k4) * 128 + j];
        ulonglong2 h[4];
#pragma unroll
        for (int i = 0; i < 4; i++)
            h[i] = *reinterpret_cast<const ulonglong2*>(&hs[r0 + i][k4 * 4]);
#pragma unroll
        for (int i = 0; i < 4; i++) {
            ffma2(ar[i],  h[i].x, w0.u.x); ffma2(az[i],  h[i].x, w1.u.x);
            ffma2(anh[i], h[i].x, w2.u.x);
            ffma2(ar[i],  h[i].y, w0.u.y); ffma2(az[i],  h[i].y, w1.u.y);
            ffma2(anh[i], h[i].y, w2.u.y);
        }
    }

    const float4* WI = reinterpret_cast<const float4*>(wiP);
#pragma unroll 2
    for (int k4 = 0; k4 < Odim / 4; k4++) {
        F4U w0, w1, w2;
        w0.f = WI[(size_t)(0 * 8 + k4) * 128 + j];
        w1.f = WI[(size_t)(1 * 8 + k4) * 128 + j];
        w2.f = WI[(size_t)(2 * 8 + k4) * 128 + j];
        ulonglong2 p[4];
#pragma unroll
        for (int i = 0; i < 4; i++)
            p[i] = *reinterpret_cast<const ulonglong2*>(&ps[r0 + i][k4 * 4]);
#pragma unroll
        for (int i = 0; i < 4; i++) {
            ffma2(ar[i],  p[i].x, w0.u.x); ffma2(az[i],  p[i].x, w1.u.x);
            ffma2(anx[i], p[i].x, w2.u.x);
            ffma2(ar[i],  p[i].y, w0.u.y); ffma2(az[i],  p[i].y, w1.u.y);
            ffma2(anx[i], p[i].y, w2.u.y);
        }
    }

#pragma unroll
    for (int i = 0; i < 4; i++) {
        float rg = sigmoidf_(f2sum(ar[i]));
        float zg = sigmoidf_(f2sum(az[i]));
        float n  = tanhf(f2sum(anx[i]) + rg * f2sum(anh[i]));
        float hv = hs[r0 + i][j];
        out[i] = (1.0f - zg) * n + zg * hv;
    }
}

// ---------------- fused node kernel ---------------------------------------
__global__ void __launch_bounds__(NTHR)
node_kernel(const float* __restrict__ h_a,
            const float* __restrict__ h2o_w, const float* __restrict__ h2o_b,
            const float* __restrict__ wiP,   const float* __restrict__ bi,
            const float* __restrict__ whP,   const float* __restrict__ bh,
            float* __restrict__ pred_out, float* __restrict__ probs_out,
            float* __restrict__ h_out) {
    __shared__ float hs[RB][Hdim];
    __shared__ float ps[RB][Odim];
    const int t    = threadIdx.x;
    const int row0 = blockIdx.x * RB;

    {
        const float4* src = reinterpret_cast<const float4*>(h_a + (size_t)row0 * Hdim);
        float4* dst = reinterpret_cast<float4*>(&hs[0][0]);
        for (int i = t; i < RB * Hdim / 4; i += NTHR) dst[i] = src[i];
    }
    __syncthreads();

    // ---- pred + softmax: warp w handles rows w*4..w*4+3, lane = o ----
    {
        const int o = t & 31, w = t >> 5;
        float acc[4];
        const float bb = h2o_b[o];
#pragma unroll
        for (int i = 0; i < 4; i++) acc[i] = bb;
        for (int k = 0; k < Hdim; k += 4) {
            float4 hv[4];
#pragma unroll
            for (int i = 0; i < 4; i++)
                hv[i] = *reinterpret_cast<const float4*>(&hs[w * 4 + i][k]);
#pragma unroll
            for (int kk = 0; kk < 4; kk++) {
                float wv = h2o_w[(size_t)(k + kk) * Odim + o];
#pragma unroll
                for (int i = 0; i < 4; i++) {
                    float h = (kk == 0) ? hv[i].x : (kk == 1) ? hv[i].y
                              : (kk == 2) ? hv[i].z : hv[i].w;
                    acc[i] += h * wv;
                }
            }
        }
#pragma unroll
        for (int i = 0; i < 4; i++) {
            int r = w * 4 + i;
            float v = acc[i];
            pred_out[(size_t)(row0 + r) * Odim + o] = v;
            float m = v;
#pragma unroll
            for (int s = 16; s > 0; s >>= 1)
                m = fmaxf(m, __shfl_xor_sync(0xffffffffu, m, s));
            float e = expf(v - m);
            float ssum = e;
#pragma unroll
            for (int s = 16; s > 0; s >>= 1)
                ssum += __shfl_xor_sync(0xffffffffu, ssum, s);
            float p = e / ssum;
            ps[r][o] = p;
            probs_out[(size_t)(row0 + r) * Odim + o] = p;
        }
    }
    __syncthreads();

    const int j = t;
    for (int r0 = 0; r0 < RB; r0 += 4) {
        float out[4];
        gru_rows4(hs, ps, r0, j, whP, wiP, bi, bh, out);
#pragma unroll
        for (int i = 0; i < 4; i++)
            h_out[(size_t)(row0 + r0 + i) * Hdim + j] = out[i];
    }
}

// ---------------- fused combine kernel ------------------------------------
__global__ void __launch_bounds__(NTHR)
combine_kernel(const float* __restrict__ probs_fc,
               const float* __restrict__ h_ai, const float* __restrict__ h_a,
               const float* __restrict__ wiP,  const float* __restrict__ bi,
               const float* __restrict__ whP,  const float* __restrict__ bh,
               const float* __restrict__ ufP,  const float* __restrict__ ufb,
               const float* __restrict__ uaP,  const float* __restrict__ uab,
               float* __restrict__ h2_out) {
    __shared__ float hs[RB][Hdim];   // h_ai, later reloaded with h_a
    __shared__ float ps[RB][Odim];
    __shared__ float hf[RB][Hdim];
    const int t    = threadIdx.x;
    const int row0 = blockIdx.x * RB;

    {
        const float4* src = reinterpret_cast<const float4*>(h_ai + (size_t)row0 * Hdim);
        float4* dst = reinterpret_cast<float4*>(&hs[0][0]);
        for (int i = t; i < RB * Hdim / 4; i += NTHR) dst[i] = src[i];
        const float4* psrc = reinterpret_cast<const float4*>(probs_fc + (size_t)row0 * Odim);
        float4* pdst = reinterpret_cast<float4*>(&ps[0][0]);
        for (int i = t; i < RB * Odim / 4; i += NTHR) pdst[i] = psrc[i];
    }
    __syncthreads();

    const int j = t;
    for (int r0 = 0; r0 < RB; r0 += 4) {
        float out[4];
        gru_rows4(hs, ps, r0, j, whP, wiP, bi, bh, out);
#pragma unroll
        for (int i = 0; i < 4; i++)
            hf[r0 + i][j] = out[i];
    }
    __syncthreads();
    // reload hs with h_a
    {
        const float4* src = reinterpret_cast<const float4*>(h_a + (size_t)row0 * Hdim);
        float4* dst = reinterpret_cast<float4*>(&hs[0][0]);
        for (int i = t; i < RB * Hdim / 4; i += NTHR) dst[i] = src[i];
    }
    __syncthreads();

    // h2 = tanh(hf@ufw + hs@uaw + ufb + uab)  — packed FFMA2
    const float bb = ufb[j] + uab[j];
    const float4* UF = reinterpret_cast<const float4*>(ufP);
    const float4* UA = reinterpret_cast<const float4*>(uaP);
    for (int r0 = 0; r0 < RB; r0 += 4) {
        u64 acc[4];
#pragma unroll
        for (int i = 0; i < 4; i++) acc[i] = pack2(bb, 0.0f);
#pragma unroll 2
        for (int k4 = 0; k4 < Hdim / 4; k4++) {
            F4U wf, wa;
            wf.f = UF[(size_t)k4 * 128 + j];
            wa.f = UA[(size_t)k4 * 128 + j];
            ulonglong2 hv[4], av[4];
#pragma unroll
            for (int i = 0; i < 4; i++) {
                hv[i] = *reinterpret_cast<const ulonglong2*>(&hf[r0 + i][k4 * 4]);
                av[i] = *reinterpret_cast<const ulonglong2*>(&hs[r0 + i][k4 * 4]);
            }
#pragma unroll
            for (int i = 0; i < 4; i++) {
                ffma2(acc[i], hv[i].x, wf.u.x); ffma2(acc[i], hv[i].y, wf.u.y);
                ffma2(acc[i], av[i].x, wa.u.x); ffma2(acc[i], av[i].y, wa.u.y);
            }
        }
#pragma unroll
        for (int i = 0; i < 4; i++)
            h2_out[(size_t)(row0 + r0 + i) * Hdim + j] = tanhf(f2sum(acc[i]));
    }
}

// ---------------- host-side tree orchestration ----------------------------
struct EmitCtx {
    const float *h2o_w, *h2o_b;
    const float *abi, *abh, *fbi, *fbh;
    const float *uab, *ufb;
    const float *awiP, *awhP, *fwiP, *fwhP, *ufP, *uaP;
    float* out;
    float *HAI, *H2, *PR;
    int B, grid, idx;
};

static void emit_node(EmitCtx& P, int lvl, int d, const float* h_in) {
    float* probs = P.PR  + (size_t)lvl * P.B * Odim;
    float* h_ai  = P.HAI + (size_t)lvl * P.B * Hdim;
    node_kernel<<<P.grid, NTHR>>>(h_in, P.h2o_w, P.h2o_b,
                                  P.awiP, P.abi, P.awhP, P.abh,
                                  P.out + (size_t)P.idx * P.B * Odim,
                                  probs, h_ai);
    P.idx++;
    if (d > 0) {
        emit_node(P, lvl + 1, d - 1, h_ai);
        float* h2 = P.H2 + (size_t)lvl * P.B * Hdim;
        combine_kernel<<<P.grid, NTHR>>>(P.PR + (size_t)(lvl + 1) * P.B * Odim,
                                         h_ai, h_in,
                                         P.fwiP, P.fbi, P.fwhP, P.fbh,
                                         P.ufP, P.ufb, P.uaP, P.uab, h2);
        emit_node(P, lvl + 1, d - 1, h2);
    }
}

extern "C" void kernel_launch(void* const* d_in, const int* in_sizes, int n_in,
                              void* d_out, int out_size) {
    const float* z      = (const float*)d_in[0];
    const float* z2h_w  = (const float*)d_in[1];
    const float* z2h_b  = (const float*)d_in[2];

    const float* h2o_w  = (const float*)d_in[3];
    const float* h2o_b  = (const float*)d_in[4];
    const float* awi    = (const float*)d_in[5];
    const float* abi    = (const float*)d_in[6];
    const float* awh    = (const float*)d_in[7];
    const float* abh    = (const float*)d_in[8];
    const float* fwi    = (const float*)d_in[9];
    const float* fbi    = (const float*)d_in[10];
    const float* fwh    = (const float*)d_in[11];
    const float* fbh    = (const float*)d_in[12];
    const float* uaw    = (const float*)d_in[13];
    const float* uab    = (const float*)d_in[14];
    const float* ufw    = (const float*)d_in[15];
    const float* ufb    = (const float*)d_in[16];

    const int H  = in_sizes[2];               // 128
    const int O  = in_sizes[4];               // 32
    const int IN = in_sizes[1] / H;           // 64
    const int B  = in_sizes[0] / IN;          // 16384
    const int nn = out_size / (B * O);        // tree nodes (31)
    int depth = 0;
    while (((2 << depth) - 1) < nn) depth++;

    float *H0p, *HAIp, *H2p, *PRp, *WPp;
    cudaGetSymbolAddress((void**)&H0p,  g_H0);
    cudaGetSymbolAddress((void**)&HAIp, g_HAI);
    cudaGetSymbolAddress((void**)&H2p,  g_H2);
    cudaGetSymbolAddress((void**)&PRp,  g_PR);
    cudaGetSymbolAddress((void**)&WPp,  g_WP);

    // weight repack prologue (38912 float4 groups)
    pack_kernel<<<(38912 + 255) / 256, 256>>>(awh, awi, fwh, fwi, ufw, uaw, WPp);

    EmitCtx P;
    P.h2o_w = h2o_w; P.h2o_b = h2o_b;
    P.abi = abi; P.abh = abh; P.fbi = fbi; P.fbh = fbh;
    P.uab = uab; P.ufb = ufb;
    P.awiP = WPp + OFF_WI_A; P.awhP = WPp + OFF_WH_A;
    P.fwiP = WPp + OFF_WI_F; P.fwhP = WPp + OFF_WH_F;
    P.ufP  = WPp + OFF_UF;   P.uaP  = WPp + OFF_UA;
    P.out  = (float*)d_out;
    P.HAI = HAIp; P.H2 = H2p; P.PR = PRp;
    P.B = B; P.grid = B / RB; P.idx = 0;

    init_kernel<<<P.grid, NTHR>>>(z, z2h_w, z2h_b, H0p);
    emit_node(P, 0, depth, H0p);
}

// round 5
// speedup vs baseline: 1.5221x; 1.2747x over previous
#include <cuda_runtime.h>

// ---------------- problem constants ---------------------------------------
#define Hdim   128
#define Odim   32
#define INdim  64
#define RB     8           // batch rows per block (single register pass)
#define NTHR   128
#define MAXB   16384
#define MAXLVL 6

// ---------------- static device scratch -----------------------------------
__device__ float g_H0 [(size_t)MAXB * Hdim];
__device__ float g_HAI[(size_t)MAXLVL * MAXB * Hdim];
__device__ float g_H2 [(size_t)MAXLVL * MAXB * Hdim];
__device__ float g_PR [(size_t)(MAXLVL + 1) * MAXB * Odim];

// packed weights: [k4][j][4] per matrix (gates folded into k)
#define OFF_WH_A 0
#define OFF_WI_A 49152
#define OFF_WH_F 61440
#define OFF_WI_F 110592
#define OFF_UF   122880
#define OFF_UA   139264
__device__ float g_WP[155648];

typedef unsigned long long u64;
union F4U { float4 f; ulonglong2 u; };

__device__ __forceinline__ void ffma2(u64& d, u64 a, u64 b) {
    asm volatile("fma.rn.f32x2 %0, %1, %2, %0;" : "+l"(d) : "l"(a), "l"(b));
}
__device__ __forceinline__ u64 pack2(float lo, float hi) {
    u64 r; asm("mov.b64 %0, {%1, %2};" : "=l"(r) : "f"(lo), "f"(hi)); return r;
}
__device__ __forceinline__ float f2sum(u64 v) {
    float lo, hi; asm("mov.b64 {%0, %1}, %2;" : "=f"(lo), "=f"(hi) : "l"(v));
    return lo + hi;
}
__device__ __forceinline__ float sigmoidf_(float x) {
    return 1.0f / (1.0f + expf(-x));
}

// ---------------- weight repack prologue ----------------------------------
__device__ __forceinline__ void pack_one(const float* __restrict__ src,
                                         float* __restrict__ dst, int g) {
    int k4 = g >> 7, j = g & 127;
    float4 v;
    v.x = src[(size_t)(4 * k4 + 0) * 128 + j];
    v.y = src[(size_t)(4 * k4 + 1) * 128 + j];
    v.z = src[(size_t)(4 * k4 + 2) * 128 + j];
    v.w = src[(size_t)(4 * k4 + 3) * 128 + j];
    *reinterpret_cast<float4*>(dst + (size_t)g * 4) = v;
}

__global__ void pack_kernel(const float* __restrict__ awh, const float* __restrict__ awi,
                            const float* __restrict__ fwh, const float* __restrict__ fwi,
                            const float* __restrict__ ufw, const float* __restrict__ uaw,
                            float* __restrict__ WP) {
    int g = blockIdx.x * blockDim.x + threadIdx.x;
    if      (g < 12288) pack_one(awh, WP + OFF_WH_A, g);
    else if (g < 15360) pack_one(awi, WP + OFF_WI_A, g - 12288);
    else if (g < 27648) pack_one(fwh, WP + OFF_WH_F, g - 15360);
    else if (g < 30720) pack_one(fwi, WP + OFF_WI_F, g - 27648);
    else if (g < 34816) pack_one(ufw, WP + OFF_UF,   g - 30720);
    else if (g < 38912) pack_one(uaw, WP + OFF_UA,   g - 34816);
}

// ---------------- init: hidden = z @ z2h_w + z2h_b ------------------------
__global__ void __launch_bounds__(NTHR)
init_kernel(const float* __restrict__ z, const float* __restrict__ w,
            const float* __restrict__ b, float* __restrict__ hout) {
    __shared__ float zs[RB][INdim];
    const int j    = threadIdx.x;
    const int row0 = blockIdx.x * RB;

    {
        const float4* src = reinterpret_cast<const float4*>(z + (size_t)row0 * INdim);
        float4* dst = reinterpret_cast<float4*>(&zs[0][0]);
        for (int i = j; i < RB * INdim / 4; i += NTHR) dst[i] = src[i];
    }
    __syncthreads();

    const float bb = b[j];
    float acc[RB];
#pragma unroll
    for (int i = 0; i < RB; i++) acc[i] = bb;
#pragma unroll 4
    for (int k = 0; k < INdim; k += 4) {
        float4 hv[RB];
#pragma unroll
        for (int i = 0; i < RB; i++)
            hv[i] = *reinterpret_cast<const float4*>(&zs[i][k]);
#pragma unroll
        for (int kk = 0; kk < 4; kk++) {
            float wv = w[(size_t)(k + kk) * Hdim + j];
#pragma unroll
            for (int i = 0; i < RB; i++) {
                float h = (kk == 0) ? hv[i].x : (kk == 1) ? hv[i].y
                          : (kk == 2) ? hv[i].z : hv[i].w;
                acc[i] += h * wv;
            }
        }
    }
#pragma unroll
    for (int i = 0; i < RB; i++)
        hout[(size_t)(row0 + i) * Hdim + j] = acc[i];
}

// ---------------- GRU gate core: 8 rows, single pass, packed FFMA2 --------
// hsf: [8][128] flat smem; psf: [8][32] flat smem.
__device__ __forceinline__ void gru_rows8(
    const float* __restrict__ hsf, const float* __restrict__ psf, int j,
    const float* __restrict__ whP, const float* __restrict__ wiP,
    const float* __restrict__ bi,  const float* __restrict__ bh,
    float out[RB]) {
    const float br_ = bi[0 * Hdim + j] + bh[0 * Hdim + j];
    const float bz_ = bi[1 * Hdim + j] + bh[1 * Hdim + j];
    const float bxn = bi[2 * Hdim + j];
    const float bhn = bh[2 * Hdim + j];

    u64 ar[RB], az[RB], anh[RB], anx[RB];
#pragma unroll
    for (int i = 0; i < RB; i++) {
        ar[i]  = pack2(br_, 0.0f);
        az[i]  = pack2(bz_, 0.0f);
        anh[i] = pack2(bhn, 0.0f);
        anx[i] = pack2(bxn, 0.0f);
    }

    const float4* pw = reinterpret_cast<const float4*>(whP) + j;     // gate strides 4096
    const ulonglong2* ph = reinterpret_cast<const ulonglong2*>(hsf); // row stride 32
#pragma unroll 4
    for (int k4 = 0; k4 < Hdim / 4; k4++) {
        F4U w0, w1, w2;
        w0.f = pw[k4 * 128];
        w1.f = pw[k4 * 128 + 4096];
        w2.f = pw[k4 * 128 + 8192];
        ulonglong2 h[RB];
#pragma unroll
        for (int i = 0; i < RB; i++) h[i] = ph[i * 32 + k4];
#pragma unroll
        for (int i = 0; i < RB; i++) {
            ffma2(ar[i],  h[i].x, w0.u.x); ffma2(az[i],  h[i].x, w1.u.x);
            ffma2(anh[i], h[i].x, w2.u.x);
            ffma2(ar[i],  h[i].y, w0.u.y); ffma2(az[i],  h[i].y, w1.u.y);
            ffma2(anh[i], h[i].y, w2.u.y);
        }
    }

    const float4* pwi = reinterpret_cast<const float4*>(wiP) + j;    // gate strides 1024
    const ulonglong2* pp = reinterpret_cast<const ulonglong2*>(psf); // row stride 8
#pragma unroll
    for (int k4 = 0; k4 < Odim / 4; k4++) {
        F4U w0, w1, w2;
        w0.f = pwi[k4 * 128];
        w1.f = pwi[k4 * 128 + 1024];
        w2.f = pwi[k4 * 128 + 2048];
        ulonglong2 p[RB];
#pragma unroll
        for (int i = 0; i < RB; i++) p[i] = pp[i * 8 + k4];
#pragma unroll
        for (int i = 0; i < RB; i++) {
            ffma2(ar[i],  p[i].x, w0.u.x); ffma2(az[i],  p[i].x, w1.u.x);
            ffma2(anx[i], p[i].x, w2.u.x);
            ffma2(ar[i],  p[i].y, w0.u.y); ffma2(az[i],  p[i].y, w1.u.y);
            ffma2(anx[i], p[i].y, w2.u.y);
        }
    }

#pragma unroll
    for (int i = 0; i < RB; i++) {
        float rg = sigmoidf_(f2sum(ar[i]));
        float zg = sigmoidf_(f2sum(az[i]));
        float n  = tanhf(f2sum(anx[i]) + rg * f2sum(anh[i]));
        float hv = hsf[i * Hdim + j];
        out[i] = (1.0f - zg) * n + zg * hv;
    }
}

// ---------------- fused node kernel ---------------------------------------
__global__ void __launch_bounds__(NTHR, 4)
node_kernel(const float* __restrict__ h_a,
            const float* __restrict__ h2o_w, const float* __restrict__ h2o_b,
            const float* __restrict__ wiP,   const float* __restrict__ bi,
            const float* __restrict__ whP,   const float* __restrict__ bh,
            float* __restrict__ pred_out, float* __restrict__ probs_out,
            float* __restrict__ h_out) {
    __shared__ float hs[RB * Hdim];
    __shared__ float ps[RB * Odim];
    const int t    = threadIdx.x;
    const int row0 = blockIdx.x * RB;

    {
        const float4* src = reinterpret_cast<const float4*>(h_a + (size_t)row0 * Hdim);
        float4* dst = reinterpret_cast<float4*>(hs);
#pragma unroll
        for (int i = t; i < RB * Hdim / 4; i += NTHR) dst[i] = src[i];
    }
    __syncthreads();

    // ---- pred + softmax: warp w handles rows 2w, 2w+1; lane = o ----
    {
        const int o = t & 31, w = t >> 5;
        float acc[2];
        const float bb = h2o_b[o];
        acc[0] = bb; acc[1] = bb;
#pragma unroll 4
        for (int k = 0; k < Hdim; k += 4) {
            float4 h0 = *reinterpret_cast<const float4*>(&hs[(w * 2 + 0) * Hdim + k]);
            float4 h1 = *reinterpret_cast<const float4*>(&hs[(w * 2 + 1) * Hdim + k]);
#pragma unroll
            for (int kk = 0; kk < 4; kk++) {
                float wv = h2o_w[(size_t)(k + kk) * Odim + o];
                float a0 = (kk == 0) ? h0.x : (kk == 1) ? h0.y : (kk == 2) ? h0.z : h0.w;
                float a1 = (kk == 0) ? h1.x : (kk == 1) ? h1.y : (kk == 2) ? h1.z : h1.w;
                acc[0] += a0 * wv;
                acc[1] += a1 * wv;
            }
        }
#pragma unroll
        for (int i = 0; i < 2; i++) {
            int r = w * 2 + i;
            float v = acc[i];
            pred_out[(size_t)(row0 + r) * Odim + o] = v;
            float m = v;
#pragma unroll
            for (int s = 16; s > 0; s >>= 1)
                m = fmaxf(m, __shfl_xor_sync(0xffffffffu, m, s));
            float e = expf(v - m);
            float ssum = e;
#pragma unroll
            for (int s = 16; s > 0; s >>= 1)
                ssum += __shfl_xor_sync(0xffffffffu, ssum, s);
            float p = e / ssum;
            ps[r * Odim + o] = p;
            probs_out[(size_t)(row0 + r) * Odim + o] = p;
        }
    }
    __syncthreads();

    float out[RB];
    gru_rows8(hs, ps, t, whP, wiP, bi, bh, out);
    {
        float* po = h_out + (size_t)row0 * Hdim + t;
#pragma unroll
        for (int i = 0; i < RB; i++) po[i * Hdim] = out[i];
    }
}

// ---------------- fused combine kernel ------------------------------------
__global__ void __launch_bounds__(NTHR, 4)
combine_kernel(const float* __restrict__ probs_fc,
               const float* __restrict__ h_ai, const float* __restrict__ h_a,
               const float* __restrict__ wiP,  const float* __restrict__ bi,
               const float* __restrict__ whP,  const float* __restrict__ bh,
               const float* __restrict__ ufP,  const float* __restrict__ ufb,
               const float* __restrict__ uaP,  const float* __restrict__ uab,
               float* __restrict__ h2_out) {
    __shared__ float hs[RB * Hdim];   // h_ai, later reloaded with h_a
    __shared__ float ps[RB * Odim];
    __shared__ float hf[RB * Hdim];
    const int t    = threadIdx.x;
    const int row0 = blockIdx.x * RB;

    {
        const float4* src = reinterpret_cast<const float4*>(h_ai + (size_t)row0 * Hdim);
        float4* dst = reinterpret_cast<float4*>(hs);
#pragma unroll
        for (int i = t; i < RB * Hdim / 4; i += NTHR) dst[i] = src[i];
        const float4* psrc = reinterpret_cast<const float4*>(probs_fc + (size_t)row0 * Odim);
        float4* pdst = reinterpret_cast<float4*>(ps);
        if (t < RB * Odim / 4) pdst[t] = psrc[t];
    }
    __syncthreads();

    float out[RB];
    gru_rows8(hs, ps, t, whP, wiP, bi, bh, out);
#pragma unroll
    for (int i = 0; i < RB; i++) hf[i * Hdim + t] = out[i];
    __syncthreads();
    // reload hs with h_a
    {
        const float4* src = reinterpret_cast<const float4*>(h_a + (size_t)row0 * Hdim);
        float4* dst = reinterpret_cast<float4*>(hs);
#pragma unroll
        for (int i = t; i < RB * Hdim / 4; i += NTHR) dst[i] = src[i];
    }
    __syncthreads();

    // h2 = tanh(hf@ufw + hs@uaw + ufb + uab)
    const float bb = ufb[t] + uab[t];
    u64 acc[RB];
#pragma unroll
    for (int i = 0; i < RB; i++) acc[i] = pack2(bb, 0.0f);

    const float4* pf = reinterpret_cast<const float4*>(ufP) + t;
    const float4* pa = reinterpret_cast<const float4*>(uaP) + t;
    const ulonglong2* phf = reinterpret_cast<const ulonglong2*>(hf);
    const ulonglong2* phs = reinterpret_cast<const ulonglong2*>(hs);
#pragma unroll 4
    for (int k4 = 0; k4 < Hdim / 4; k4++) {
        F4U wf, wa;
        wf.f = pf[k4 * 128];
        wa.f = pa[k4 * 128];
        ulonglong2 hv[RB], av[RB];
#pragma unroll
        for (int i = 0; i < RB; i++) {
            hv[i] = phf[i * 32 + k4];
            av[i] = phs[i * 32 + k4];
        }
#pragma unroll
        for (int i = 0; i < RB; i++) {
            ffma2(acc[i], hv[i].x, wf.u.x); ffma2(acc[i], hv[i].y, wf.u.y);
            ffma2(acc[i], av[i].x, wa.u.x); ffma2(acc[i], av[i].y, wa.u.y);
        }
    }
    {
        float* po = h2_out + (size_t)row0 * Hdim + t;
#pragma unroll
        for (int i = 0; i < RB; i++) po[i * Hdim] = tanhf(f2sum(acc[i]));
    }
}

// ---------------- host-side tree orchestration (single stream) ------------
struct EmitCtx {
    const float *h2o_w, *h2o_b;
    const float *abi, *abh, *fbi, *fbh;
    const float *uab, *ufb;
    const float *awiP, *awhP, *fwiP, *fwhP, *ufP, *uaP;
    float* out;
    float *HAI, *H2, *PR;
    int B, grid, idx;
};

static void emit_node(EmitCtx& P, int lvl, int d, const float* h_in) {
    float* probs = P.PR  + (size_t)lvl * P.B * Odim;
    float* h_ai  = P.HAI + (size_t)lvl * P.B * Hdim;
    node_kernel<<<P.grid, NTHR>>>(h_in, P.h2o_w, P.h2o_b,
                                  P.awiP, P.abi, P.awhP, P.abh,
                                  P.out + (size_t)P.idx * P.B * Odim,
                                  probs, h_ai);
    P.idx++;
    if (d > 0) {
        emit_node(P, lvl + 1, d - 1, h_ai);
        float* h2 = P.H2 + (size_t)lvl * P.B * Hdim;
        combine_kernel<<<P.grid, NTHR>>>(P.PR + (size_t)(lvl + 1) * P.B * Odim,
                                         h_ai, h_in,
                                         P.fwiP, P.fbi, P.fwhP, P.fbh,
                                         P.ufP, P.ufb, P.uaP, P.uab, h2);
        emit_node(P, lvl + 1, d - 1, h2);
    }
}

extern "C" void kernel_launch(void* const* d_in, const int* in_sizes, int n_in,
                              void* d_out, int out_size) {
    const float* z      = (const float*)d_in[0];
    const float* z2h_w  = (const float*)d_in[1];
    const float* z2h_b  = (const float*)d_in[2];
    const float* h2o_w  = (const float*)d_in[3];
    const float* h2o_b  = (const float*)d_in[4];
    const float* awi    = (const float*)d_in[5];
    const float* abi    = (const float*)d_in[6];
    const float* awh    = (const float*)d_in[7];
    const float* abh    = (const float*)d_in[8];
    const float* fwi    = (const float*)d_in[9];
    const float* fbi    = (const float*)d_in[10];
    const float* fwh    = (const float*)d_in[11];
    const float* fbh    = (const float*)d_in[12];
    const float* uaw    = (const float*)d_in[13];
    const float* uab    = (const float*)d_in[14];
    const float* ufw    = (const float*)d_in[15];
    const float* ufb    = (const float*)d_in[16];

    const int H  = in_sizes[2];               // 128
    const int O  = in_sizes[4];               // 32
    const int IN = in_sizes[1] / H;           // 64
    const int B  = in_sizes[0] / IN;          // 16384
    const int nn = out_size / (B * O);        // tree nodes (31)
    int depth = 0;
    while (((2 << depth) - 1) < nn) depth++;

    float *H0p, *HAIp, *H2p, *PRp, *WPp;
    cudaGetSymbolAddress((void**)&H0p,  g_H0);
    cudaGetSymbolAddress((void**)&HAIp, g_HAI);
    cudaGetSymbolAddress((void**)&H2p,  g_H2);
    cudaGetSymbolAddress((void**)&PRp,  g_PR);
    cudaGetSymbolAddress((void**)&WPp,  g_WP);

    pack_kernel<<<(38912 + 255) / 256, 256>>>(awh, awi, fwh, fwi, ufw, uaw, WPp);
    init_kernel<<<B / RB, NTHR>>>(z, z2h_w, z2h_b, H0p);

    EmitCtx P;
    P.h2o_w = h2o_w; P.h2o_b = h2o_b;
    P.abi = abi; P.abh = abh; P.fbi = fbi; P.fbh = fbh;
    P.uab = uab; P.ufb = ufb;
    P.awiP = WPp + OFF_WI_A; P.awhP = WPp + OFF_WH_A;
    P.fwiP = WPp + OFF_WI_F; P.fwhP = WPp + OFF_WH_F;
    P.ufP  = WPp + OFF_UF;   P.uaP  = WPp + OFF_UA;
    P.out  = (float*)d_out;
    P.HAI = HAIp; P.H2 = H2p; P.PR = PRp;
    P.B = B; P.grid = B / RB; P.idx = 0;

    emit_node(P, 0, depth, H0p);
}